// round 1
// baseline (speedup 1.0000x reference)
#include <cuda_runtime.h>
#include <cuda_bf16.h>
#include <cstdint>

// ---------------------------------------------------------------------------
// Problem constants
// ---------------------------------------------------------------------------
#define BATCH   2
#define SEQ     3072
#define DMODEL  512
#define NHEADS  8
#define DHEAD   64
#define MROWS   (BATCH * SEQ)      // 6144
#define MAXNB   32
#define CAP     256                // radius-candidate buffer per row (E[count]~36)

typedef unsigned long long u64;

// ---------------------------------------------------------------------------
// Scratch (static device memory; no allocations allowed)
// ---------------------------------------------------------------------------
__device__ float g_Q[MROWS * DMODEL];
__device__ float g_K[MROWS * DMODEL];
__device__ float g_V[MROWS * DMODEL];
__device__ float g_A[MROWS * DMODEL];
__device__ int   g_nbr[MROWS * MAXNB];
__device__ int   g_cnt[MROWS];

// ---------------------------------------------------------------------------
// Packed f32x2 helpers (Blackwell full-rate fp32 path)
// ---------------------------------------------------------------------------
__device__ __forceinline__ void fma2(u64 &c, u64 a, u64 b) {
    asm("fma.rn.f32x2 %0, %1, %2, %0;" : "+l"(c) : "l"(a), "l"(b));
}
__device__ __forceinline__ void unpack2(u64 v, float &lo, float &hi) {
    asm("mov.b64 {%0, %1}, %2;" : "=f"(lo), "=f"(hi) : "l"(v));
}

// ---------------------------------------------------------------------------
// SGEMM: C[M=6144, N=512] = A[6144,512] @ W[512,512] + bias
// 128x128 tile, BK=16, 256 threads, 8x8 per thread.
// Accumulators packed as f32x2 pairs along M; B stored DUPLICATED in smem so
// (b,b) pairs come straight out of LDS.128 (no packing MOVs in inner loop).
// ---------------------------------------------------------------------------
#define BM 128
#define BN 128
#define BKK 16
#define AS_STRIDE 132     // 128 + 4 pad (16B-aligned rows, fewer STS conflicts)
#define BS_STRIDE 264     // 2*128 + 8 pad

__device__ __forceinline__ void gemm_tile_body(const float* __restrict__ A,
                                               const float* __restrict__ W,
                                               const float* __restrict__ bias,
                                               float* __restrict__ C)
{
    __shared__ float As[BKK * AS_STRIDE];
    __shared__ float Bs[BKK * BS_STRIDE];

    const int tid = threadIdx.x;          // 256 threads
    const int tx  = tid & 15;             // col group (8 cols each)
    const int ty  = tid >> 4;             // row group (8 rows each)
    const int m0  = blockIdx.y * BM;
    const int n0  = blockIdx.x * BN;

    // A-tile loader mapping: 128 rows x 16 cols, 2 float4 per thread
    const int a_row = tid >> 2;           // 0..63
    const int a_col = (tid & 3) << 2;     // 0,4,8,12
    // B-tile loader mapping: 16 rows x 128 cols, 2 float4 per thread
    const int b_kr  = tid >> 5;           // 0..7
    const int b_col = (tid & 31) << 2;    // 0..124

    u64 acc[4][8];
    #pragma unroll
    for (int i = 0; i < 4; ++i)
        #pragma unroll
        for (int j = 0; j < 8; ++j) acc[i][j] = 0ull;

    const float* Aptr = A + (m0 + a_row) * DMODEL + a_col;
    const float* Wptr = W + b_kr * DMODEL + n0 + b_col;

    for (int kt = 0; kt < DMODEL / BKK; ++kt) {
        const float4 av0 = *(const float4*)(Aptr + kt * BKK);
        const float4 av1 = *(const float4*)(Aptr + 64 * DMODEL + kt * BKK);
        const float4 bv0 = *(const float4*)(Wptr + (kt * BKK) * DMODEL);
        const float4 bv1 = *(const float4*)(Wptr + (kt * BKK + 8) * DMODEL);

        __syncthreads();   // previous tile consumed

        // A stored transposed: As[k][row]
        As[(a_col + 0) * AS_STRIDE + a_row]      = av0.x;
        As[(a_col + 1) * AS_STRIDE + a_row]      = av0.y;
        As[(a_col + 2) * AS_STRIDE + a_row]      = av0.z;
        As[(a_col + 3) * AS_STRIDE + a_row]      = av0.w;
        As[(a_col + 0) * AS_STRIDE + a_row + 64] = av1.x;
        As[(a_col + 1) * AS_STRIDE + a_row + 64] = av1.y;
        As[(a_col + 2) * AS_STRIDE + a_row + 64] = av1.z;
        As[(a_col + 3) * AS_STRIDE + a_row + 64] = av1.w;

        // B stored duplicated: Bs[k][2c] = Bs[k][2c+1] = W[k][c]
        {
            float* bd = &Bs[b_kr * BS_STRIDE + 2 * b_col];
            ((float4*)bd)[0] = make_float4(bv0.x, bv0.x, bv0.y, bv0.y);
            ((float4*)bd)[1] = make_float4(bv0.z, bv0.z, bv0.w, bv0.w);
            float* bd2 = &Bs[(b_kr + 8) * BS_STRIDE + 2 * b_col];
            ((float4*)bd2)[0] = make_float4(bv1.x, bv1.x, bv1.y, bv1.y);
            ((float4*)bd2)[1] = make_float4(bv1.z, bv1.z, bv1.w, bv1.w);
        }
        __syncthreads();

        #pragma unroll
        for (int k = 0; k < BKK; ++k) {
            const ulonglong2* ap = (const ulonglong2*)(As + k * AS_STRIDE + ty * 8);
            const ulonglong2* bp = (const ulonglong2*)(Bs + k * BS_STRIDE + tx * 16);
            ulonglong2 a01 = ap[0], a23 = ap[1];
            ulonglong2 b01 = bp[0], b23 = bp[1], b45 = bp[2], b67 = bp[3];
            u64 ar[4] = { a01.x, a01.y, a23.x, a23.y };
            u64 br[8] = { b01.x, b01.y, b23.x, b23.y, b45.x, b45.y, b67.x, b67.y };
            #pragma unroll
            for (int i = 0; i < 4; ++i)
                #pragma unroll
                for (int j = 0; j < 8; ++j)
                    fma2(acc[i][j], ar[i], br[j]);
        }
    }

    // epilogue: unpack pairs (rows 2i, 2i+1), add bias, vectorized store
    float bb[8];
    #pragma unroll
    for (int j = 0; j < 8; ++j) bb[j] = bias[n0 + tx * 8 + j];

    #pragma unroll
    for (int ip = 0; ip < 4; ++ip) {
        float r0v[8], r1v[8];
        #pragma unroll
        for (int j = 0; j < 8; ++j) {
            float lo, hi;
            unpack2(acc[ip][j], lo, hi);
            r0v[j] = lo + bb[j];
            r1v[j] = hi + bb[j];
        }
        const int row0 = m0 + ty * 8 + ip * 2;
        float* c0 = C + row0 * DMODEL + n0 + tx * 8;
        ((float4*)c0)[0] = make_float4(r0v[0], r0v[1], r0v[2], r0v[3]);
        ((float4*)c0)[1] = make_float4(r0v[4], r0v[5], r0v[6], r0v[7]);
        float* c1 = c0 + DMODEL;
        ((float4*)c1)[0] = make_float4(r1v[0], r1v[1], r1v[2], r1v[3]);
        ((float4*)c1)[1] = make_float4(r1v[4], r1v[5], r1v[6], r1v[7]);
    }
}

__global__ void __launch_bounds__(256, 2)
gemm_qkv_kernel(const float* __restrict__ x,
                const float* __restrict__ Wq, const float* __restrict__ Wk,
                const float* __restrict__ Wv,
                const float* __restrict__ bq, const float* __restrict__ bk,
                const float* __restrict__ bv)
{
    const float* W; const float* bias; float* C;
    if (blockIdx.z == 0)      { W = Wq; bias = bq; C = g_Q; }
    else if (blockIdx.z == 1) { W = Wk; bias = bk; C = g_K; }
    else                      { W = Wv; bias = bv; C = g_V; }
    gemm_tile_body(x, W, bias, C);
}

__global__ void __launch_bounds__(256, 2)
gemm_out_kernel(const float* __restrict__ Wo, const float* __restrict__ bo,
                float* __restrict__ out)
{
    gemm_tile_body(g_A, Wo, bo, out);
}

// ---------------------------------------------------------------------------
// Top-k neighbor selection.
// Per warp = one query row. Radius-filter (ballot compaction) into smem, then
// (only if >32 survivors) 32x stable min-extraction on (dist_bits<<32)|idx
// keys — exactly matches stable argsort top-32 intersected with radius mask.
// ---------------------------------------------------------------------------
__global__ void __launch_bounds__(256)
topk_kernel(const float* __restrict__ positions)
{
    extern __shared__ float smem[];
    float* px = smem;
    float* py = smem + SEQ;
    float* pz = smem + 2 * SEQ;
    u64*  cand = (u64*)(smem + 3 * SEQ);

    const int tid  = threadIdx.x;
    const int warp = tid >> 5;
    const int lane = tid & 31;
    const int r0   = blockIdx.x * 8;           // 8 rows per CTA (same batch)
    const int b    = r0 / SEQ;
    const int sbase = b * SEQ;

    for (int i = tid; i < SEQ; i += 256) {
        const float* p = positions + (size_t)(sbase + i) * 3;
        px[i] = p[0]; py[i] = p[1]; pz[i] = p[2];
    }
    __syncthreads();

    const int row = r0 + warp;
    const int si  = row - sbase;
    const float qx = px[si], qy = py[si], qz = pz[si];
    u64* mycand = cand + warp * CAP;

    int cnt = 0;
    for (int t = 0; t < SEQ / 32; ++t) {
        const int j = t * 32 + lane;
        const float dx = px[j] - qx, dy = py[j] - qy, dz = pz[j] - qz;
        const float dist = sqrtf(dx * dx + dy * dy + dz * dz);
        const bool in = dist < 0.5f;
        const unsigned msk = __ballot_sync(0xffffffffu, in);
        if (in) {
            const int pos = cnt + __popc(msk & ((1u << lane) - 1u));
            if (pos < CAP)
                mycand[pos] = ((u64)__float_as_uint(dist) << 32) | (unsigned)j;
        }
        cnt += __popc(msk);
    }
    if (cnt > CAP) cnt = CAP;
    __syncwarp();

    if (cnt <= MAXNB) {
        if (lane < cnt)
            g_nbr[row * MAXNB + lane] = sbase + (int)(mycand[lane] & 0xffffffffull);
        if (lane == 0) g_cnt[row] = cnt;
    } else {
        for (int sel = 0; sel < MAXNB; ++sel) {
            u64 best = ~0ull; int bslot = 0;
            for (int s2 = lane; s2 < cnt; s2 += 32) {
                const u64 kk = mycand[s2];
                if (kk < best) { best = kk; bslot = s2; }
            }
            #pragma unroll
            for (int off = 16; off; off >>= 1) {
                const u64 ob = __shfl_xor_sync(0xffffffffu, best, off);
                const int os = __shfl_xor_sync(0xffffffffu, bslot, off);
                if (ob < best) { best = ob; bslot = os; }
            }
            if (lane == 0) {
                g_nbr[row * MAXNB + sel] = sbase + (int)(best & 0xffffffffull);
                mycand[bslot] = ~0ull;   // remove winner
            }
            __syncwarp();
        }
        if (lane == 0) g_cnt[row] = MAXNB;
    }
}

// ---------------------------------------------------------------------------
// Sparse attention. One CTA per query row, one warp per head.
// Lane j owns neighbor j's score (q broadcast from smem, full-MLP float4
// gather of K rows); softmax across lanes; AV via broadcast-shfl with lane
// owning 2 output dims.
// ---------------------------------------------------------------------------
__global__ void __launch_bounds__(256)
attn_kernel()
{
    const int row = blockIdx.x;
    __shared__ int   s_nbr[MAXNB];
    __shared__ float s_q[NHEADS][DHEAD];

    const int tid  = threadIdx.x;
    const int h    = tid >> 5;
    const int lane = tid & 31;
    const int m    = g_cnt[row];

    if (tid < MAXNB)
        s_nbr[tid] = (tid < m) ? g_nbr[row * MAXNB + tid] : 0;

    const float2 q2 = *(const float2*)&g_Q[row * DMODEL + h * DHEAD + lane * 2];
    ((float2*)s_q[h])[lane] = q2;
    __syncthreads();

    // QK: lane j computes full 64-dim dot for neighbor j
    float score = __int_as_float(0xff800000);  // -inf
    if (lane < m) {
        const float4* kp = (const float4*)&g_K[s_nbr[lane] * DMODEL + h * DHEAD];
        const float4* qp = (const float4*)&s_q[h][0];
        float acc = 0.f;
        #pragma unroll
        for (int c = 0; c < DHEAD / 4; ++c) {
            const float4 kv = kp[c];
            const float4 qv = qp[c];   // broadcast LDS
            acc += kv.x * qv.x + kv.y * qv.y + kv.z * qv.z + kv.w * qv.w;
        }
        score = acc * 0.125f;          // 1/sqrt(64)
    }

    // softmax across lanes (inactive lanes: -inf -> weight 0; m>=1 always)
    float mx = score;
    #pragma unroll
    for (int off = 16; off; off >>= 1)
        mx = fmaxf(mx, __shfl_xor_sync(0xffffffffu, mx, off));
    float p = __expf(score - mx);
    float sm = p;
    #pragma unroll
    for (int off = 16; off; off >>= 1)
        sm += __shfl_xor_sync(0xffffffffu, sm, off);
    const float pn = p / sm;

    // AV: lane owns dims (2*lane, 2*lane+1)
    float ox = 0.f, oy = 0.f;
    #pragma unroll
    for (int j = 0; j < MAXNB; ++j) {
        const float pj = __shfl_sync(0xffffffffu, pn, j);
        if (j < m) {
            const float2 v2 =
                *(const float2*)&g_V[s_nbr[j] * DMODEL + h * DHEAD + lane * 2];
            ox += pj * v2.x;
            oy += pj * v2.y;
        }
    }
    float2 o2; o2.x = ox; o2.y = oy;
    *(float2*)&g_A[row * DMODEL + h * DHEAD + lane * 2] = o2;
}

// ---------------------------------------------------------------------------
// Launch
// ---------------------------------------------------------------------------
extern "C" void kernel_launch(void* const* d_in, const int* in_sizes, int n_in,
                              void* d_out, int out_size)
{
    (void)in_sizes; (void)n_in; (void)out_size;
    const float* x   = (const float*)d_in[0];
    const float* pos = (const float*)d_in[1];
    const float* Wq  = (const float*)d_in[2];
    const float* bq  = (const float*)d_in[3];
    const float* Wk  = (const float*)d_in[4];
    const float* bk  = (const float*)d_in[5];
    const float* Wv  = (const float*)d_in[6];
    const float* bv  = (const float*)d_in[7];
    const float* Wo  = (const float*)d_in[8];
    const float* bo  = (const float*)d_in[9];
    float* out = (float*)d_out;

    const int topk_smem = 3 * SEQ * 4 + 8 * CAP * 8;  // 53248 B
    cudaFuncSetAttribute(topk_kernel,
                         cudaFuncAttributeMaxDynamicSharedMemorySize, topk_smem);

    topk_kernel<<<MROWS / 8, 256, topk_smem>>>(pos);
    gemm_qkv_kernel<<<dim3(DMODEL / BN, MROWS / BM, 3), 256>>>(x, Wq, Wk, Wv,
                                                               bq, bk, bv);
    attn_kernel<<<MROWS, 256>>>();
    gemm_out_kernel<<<dim3(DMODEL / BN, MROWS / BM, 1), 256>>>(Wo, bo, out);
}

// round 3
// speedup vs baseline: 3.2448x; 3.2448x over previous
#include <cuda_runtime.h>
#include <cuda_bf16.h>
#include <cstdint>

// ---------------------------------------------------------------------------
// Problem constants
// ---------------------------------------------------------------------------
#define BATCH   2
#define SEQ     3072
#define DMODEL  512
#define NHEADS  8
#define DHEAD   64
#define MROWS   (BATCH * SEQ)      // 6144
#define MAXNB   32
#define CAP     256

typedef unsigned long long u64;
typedef unsigned int u32;

// ---------------------------------------------------------------------------
// Scratch (static device memory; no allocations allowed)
// ---------------------------------------------------------------------------
__device__ float g_Q[MROWS * DMODEL];
__device__ float g_K[MROWS * DMODEL];
__device__ float g_V[MROWS * DMODEL];
__device__ float g_A[MROWS * DMODEL];
__device__ int   g_nbr[MROWS * MAXNB];
__device__ int   g_cnt[MROWS];

// bf16 hi/lo splits
__device__ __nv_bfloat16 g_xh[MROWS * DMODEL];
__device__ __nv_bfloat16 g_xl[MROWS * DMODEL];
__device__ __nv_bfloat16 g_ah[MROWS * DMODEL];
__device__ __nv_bfloat16 g_al[MROWS * DMODEL];
// transposed weights [n][k], 4 matrices (q,k,v,o)
__device__ __nv_bfloat16 g_wth[4 * DMODEL * DMODEL];
__device__ __nv_bfloat16 g_wtl[4 * DMODEL * DMODEL];

// ---------------------------------------------------------------------------
// hi/lo split helpers
// ---------------------------------------------------------------------------
__device__ __forceinline__ void split1(float v, __nv_bfloat16& h, __nv_bfloat16& l) {
    h = __float2bfloat16(v);
    l = __float2bfloat16(v - __bfloat162float(h));
}

__device__ __forceinline__ void split_body(const float* __restrict__ in,
                                           __nv_bfloat16* __restrict__ hi,
                                           __nv_bfloat16* __restrict__ lo)
{
    const int i = blockIdx.x * blockDim.x + threadIdx.x;   // float4 index
    const float4 v = ((const float4*)in)[i];
    __nv_bfloat16 h0, h1, h2, h3, l0, l1, l2, l3;
    split1(v.x, h0, l0); split1(v.y, h1, l1);
    split1(v.z, h2, l2); split1(v.w, h3, l3);
    __nv_bfloat162* hp = (__nv_bfloat162*)hi;
    __nv_bfloat162* lp = (__nv_bfloat162*)lo;
    hp[2 * i]     = __nv_bfloat162(h0, h1);
    hp[2 * i + 1] = __nv_bfloat162(h2, h3);
    lp[2 * i]     = __nv_bfloat162(l0, l1);
    lp[2 * i + 1] = __nv_bfloat162(l2, l3);
}

__global__ void __launch_bounds__(256)
split_x_kernel(const float* __restrict__ x) { split_body(x, g_xh, g_xl); }

__global__ void __launch_bounds__(256)
split_a_kernel() { split_body(g_A, g_ah, g_al); }

// W[k][n] -> Wt[n][k] hi/lo, 4 matrices via blockIdx.z
__global__ void __launch_bounds__(1024)
transpose_split_kernel(const float* __restrict__ Wq, const float* __restrict__ Wk,
                       const float* __restrict__ Wv, const float* __restrict__ Wo)
{
    __shared__ float t[32][33];
    const float* W = (blockIdx.z == 0) ? Wq : (blockIdx.z == 1) ? Wk
                   : (blockIdx.z == 2) ? Wv : Wo;
    __nv_bfloat16* Th = g_wth + blockIdx.z * DMODEL * DMODEL;
    __nv_bfloat16* Tl = g_wtl + blockIdx.z * DMODEL * DMODEL;

    const int n = blockIdx.x * 32 + threadIdx.x;
    const int k = blockIdx.y * 32 + threadIdx.y;
    t[threadIdx.y][threadIdx.x] = W[k * DMODEL + n];
    __syncthreads();
    const int no = blockIdx.x * 32 + threadIdx.y;
    const int ko = blockIdx.y * 32 + threadIdx.x;
    const float v = t[threadIdx.x][threadIdx.y];
    __nv_bfloat16 h, l; split1(v, h, l);
    Th[no * DMODEL + ko] = h;
    Tl[no * DMODEL + ko] = l;
}

// ---------------------------------------------------------------------------
// Tensor-core GEMM via mma.sync m16n8k16 bf16 (compute_100-safe).
// C[6144,512] = A[6144,512] @ Wt^T + bias, 3-term bf16 split:
//   A*B ~= Ah*Bh + Al*Bh + Ah*Bl   (rel err ~2^-16)
// CTA: 128x128 tile, BK=32, 256 threads = 8 warps in 4(M)x2(N), warp 32x64.
// ---------------------------------------------------------------------------
#define ASTR 40    // smem row stride in bf16 elems (80B: rows hit disjoint banks)

__device__ __forceinline__ void mma16816(float* c, const u32* a, u32 b0, u32 b1) {
    asm volatile(
        "mma.sync.aligned.m16n8k16.row.col.f32.bf16.bf16.f32 "
        "{%0,%1,%2,%3}, {%4,%5,%6,%7}, {%8,%9}, {%0,%1,%2,%3};"
        : "+f"(c[0]), "+f"(c[1]), "+f"(c[2]), "+f"(c[3])
        : "r"(a[0]), "r"(a[1]), "r"(a[2]), "r"(a[3]), "r"(b0), "r"(b1));
}

__device__ __forceinline__ void tc_gemm_body(const __nv_bfloat16* __restrict__ Ah,
                                             const __nv_bfloat16* __restrict__ Al,
                                             const __nv_bfloat16* __restrict__ Bh,
                                             const __nv_bfloat16* __restrict__ Bl,
                                             const float* __restrict__ bias,
                                             float* __restrict__ C)
{
    __shared__ __nv_bfloat16 sAh[128 * ASTR];
    __shared__ __nv_bfloat16 sAl[128 * ASTR];
    __shared__ __nv_bfloat16 sBh[128 * ASTR];
    __shared__ __nv_bfloat16 sBl[128 * ASTR];

    const int tid  = threadIdx.x;
    const int w    = tid >> 5;
    const int lane = tid & 31;
    const int g    = lane >> 2;       // 0..7
    const int t2   = (lane & 3) * 2;  // 0,2,4,6
    const int wm   = w & 3;           // M warp (32 rows)
    const int wn   = w >> 2;          // N warp (64 cols)
    const int m0   = blockIdx.y * 128;
    const int n0   = blockIdx.x * 128;

    // global loader mapping: r=tid/4 (0..63, +64), seg=tid%4 (8 cols each)
    const int lr  = tid >> 2;
    const int lc  = (tid & 3) * 8;

    float acc[2][8][4];
    #pragma unroll
    for (int i = 0; i < 2; ++i)
        #pragma unroll
        for (int j = 0; j < 8; ++j)
            #pragma unroll
            for (int q = 0; q < 4; ++q) acc[i][j][q] = 0.f;

    for (int kc = 0; kc < DMODEL / 32; ++kc) {
        const size_t eA0 = (size_t)(m0 + lr) * DMODEL + kc * 32 + lc;
        const size_t eA1 = eA0 + (size_t)64 * DMODEL;
        const size_t eB0 = (size_t)(n0 + lr) * DMODEL + kc * 32 + lc;
        const size_t eB1 = eB0 + (size_t)64 * DMODEL;
        const uint4 vah0 = *(const uint4*)(Ah + eA0);
        const uint4 vah1 = *(const uint4*)(Ah + eA1);
        const uint4 val0 = *(const uint4*)(Al + eA0);
        const uint4 val1 = *(const uint4*)(Al + eA1);
        const uint4 vbh0 = *(const uint4*)(Bh + eB0);
        const uint4 vbh1 = *(const uint4*)(Bh + eB1);
        const uint4 vbl0 = *(const uint4*)(Bl + eB0);
        const uint4 vbl1 = *(const uint4*)(Bl + eB1);

        __syncthreads();   // previous tile fully consumed
        *(uint4*)(sAh + lr * ASTR + lc)        = vah0;
        *(uint4*)(sAh + (lr + 64) * ASTR + lc) = vah1;
        *(uint4*)(sAl + lr * ASTR + lc)        = val0;
        *(uint4*)(sAl + (lr + 64) * ASTR + lc) = val1;
        *(uint4*)(sBh + lr * ASTR + lc)        = vbh0;
        *(uint4*)(sBh + (lr + 64) * ASTR + lc) = vbh1;
        *(uint4*)(sBl + lr * ASTR + lc)        = vbl0;
        *(uint4*)(sBl + (lr + 64) * ASTR + lc) = vbl1;
        __syncthreads();

        #pragma unroll
        for (int ks = 0; ks < 32; ks += 16) {
            // A fragments (m16n8k16 thread mapping)
            u32 ah[2][4], al[2][4];
            #pragma unroll
            for (int ma = 0; ma < 2; ++ma) {
                const int row = wm * 32 + ma * 16 + g;
                ah[ma][0] = *(const u32*)(sAh + row * ASTR + ks + t2);
                ah[ma][1] = *(const u32*)(sAh + (row + 8) * ASTR + ks + t2);
                ah[ma][2] = *(const u32*)(sAh + row * ASTR + ks + t2 + 8);
                ah[ma][3] = *(const u32*)(sAh + (row + 8) * ASTR + ks + t2 + 8);
                al[ma][0] = *(const u32*)(sAl + row * ASTR + ks + t2);
                al[ma][1] = *(const u32*)(sAl + (row + 8) * ASTR + ks + t2);
                al[ma][2] = *(const u32*)(sAl + row * ASTR + ks + t2 + 8);
                al[ma][3] = *(const u32*)(sAl + (row + 8) * ASTR + ks + t2 + 8);
            }
            #pragma unroll
            for (int na = 0; na < 8; ++na) {
                const int nrow = wn * 64 + na * 8 + g;
                const u32 bh0 = *(const u32*)(sBh + nrow * ASTR + ks + t2);
                const u32 bh1 = *(const u32*)(sBh + nrow * ASTR + ks + t2 + 8);
                const u32 bl0 = *(const u32*)(sBl + nrow * ASTR + ks + t2);
                const u32 bl1 = *(const u32*)(sBl + nrow * ASTR + ks + t2 + 8);
                #pragma unroll
                for (int ma = 0; ma < 2; ++ma) {
                    mma16816(acc[ma][na], ah[ma], bh0, bh1);
                    mma16816(acc[ma][na], al[ma], bh0, bh1);
                    mma16816(acc[ma][na], ah[ma], bl0, bl1);
                }
            }
        }
    }

    // epilogue
    #pragma unroll
    for (int ma = 0; ma < 2; ++ma) {
        const int row = m0 + wm * 32 + ma * 16 + g;
        #pragma unroll
        for (int na = 0; na < 8; ++na) {
            const int col = n0 + wn * 64 + na * 8 + t2;
            const float b0 = bias[col], b1 = bias[col + 1];
            float2 o0; o0.x = acc[ma][na][0] + b0; o0.y = acc[ma][na][1] + b1;
            float2 o1; o1.x = acc[ma][na][2] + b0; o1.y = acc[ma][na][3] + b1;
            *(float2*)(C + (size_t)row * DMODEL + col) = o0;
            *(float2*)(C + (size_t)(row + 8) * DMODEL + col) = o1;
        }
    }
}

__global__ void __launch_bounds__(256, 2)
gemm_qkv_kernel(const float* __restrict__ bq, const float* __restrict__ bk,
                const float* __restrict__ bv)
{
    const int z = blockIdx.z;
    const __nv_bfloat16* Bh = g_wth + (size_t)z * DMODEL * DMODEL;
    const __nv_bfloat16* Bl = g_wtl + (size_t)z * DMODEL * DMODEL;
    const float* bias = (z == 0) ? bq : (z == 1) ? bk : bv;
    float* C = (z == 0) ? g_Q : (z == 1) ? g_K : g_V;
    tc_gemm_body(g_xh, g_xl, Bh, Bl, bias, C);
}

__global__ void __launch_bounds__(256, 2)
gemm_out_kernel(const float* __restrict__ bo, float* __restrict__ out)
{
    const __nv_bfloat16* Bh = g_wth + (size_t)3 * DMODEL * DMODEL;
    const __nv_bfloat16* Bl = g_wtl + (size_t)3 * DMODEL * DMODEL;
    tc_gemm_body(g_ah, g_al, Bh, Bl, bo, out);
}

// ---------------------------------------------------------------------------
// Top-k neighbor selection (unchanged — known correct)
// ---------------------------------------------------------------------------
__global__ void __launch_bounds__(256)
topk_kernel(const float* __restrict__ positions)
{
    extern __shared__ float fsm[];
    float* px = fsm;
    float* py = fsm + SEQ;
    float* pz = fsm + 2 * SEQ;
    u64*  cand = (u64*)(fsm + 3 * SEQ);

    const int tid  = threadIdx.x;
    const int warp = tid >> 5;
    const int lane = tid & 31;
    const int r0   = blockIdx.x * 8;
    const int b    = r0 / SEQ;
    const int sbase = b * SEQ;

    for (int i = tid; i < SEQ; i += 256) {
        const float* p = positions + (size_t)(sbase + i) * 3;
        px[i] = p[0]; py[i] = p[1]; pz[i] = p[2];
    }
    __syncthreads();

    const int row = r0 + warp;
    const int si  = row - sbase;
    const float qx = px[si], qy = py[si], qz = pz[si];
    u64* mycand = cand + warp * CAP;

    int cnt = 0;
    for (int t = 0; t < SEQ / 32; ++t) {
        const int j = t * 32 + lane;
        const float dx = px[j] - qx, dy = py[j] - qy, dz = pz[j] - qz;
        const float dist = sqrtf(dx * dx + dy * dy + dz * dz);
        const bool in = dist < 0.5f;
        const unsigned msk = __ballot_sync(0xffffffffu, in);
        if (in) {
            const int pos = cnt + __popc(msk & ((1u << lane) - 1u));
            if (pos < CAP)
                mycand[pos] = ((u64)__float_as_uint(dist) << 32) | (unsigned)j;
        }
        cnt += __popc(msk);
    }
    if (cnt > CAP) cnt = CAP;
    __syncwarp();

    if (cnt <= MAXNB) {
        if (lane < cnt)
            g_nbr[row * MAXNB + lane] = sbase + (int)(mycand[lane] & 0xffffffffull);
        if (lane == 0) g_cnt[row] = cnt;
    } else {
        for (int sel = 0; sel < MAXNB; ++sel) {
            u64 best = ~0ull; int bslot = 0;
            for (int s2 = lane; s2 < cnt; s2 += 32) {
                const u64 kk = mycand[s2];
                if (kk < best) { best = kk; bslot = s2; }
            }
            #pragma unroll
            for (int off = 16; off; off >>= 1) {
                const u64 ob = __shfl_xor_sync(0xffffffffu, best, off);
                const int os = __shfl_xor_sync(0xffffffffu, bslot, off);
                if (ob < best) { best = ob; bslot = os; }
            }
            if (lane == 0) {
                g_nbr[row * MAXNB + sel] = sbase + (int)(best & 0xffffffffull);
                mycand[bslot] = ~0ull;
            }
            __syncwarp();
        }
        if (lane == 0) g_cnt[row] = MAXNB;
    }
}

// ---------------------------------------------------------------------------
// Sparse attention (unchanged — known correct)
// ---------------------------------------------------------------------------
__global__ void __launch_bounds__(256)
attn_kernel()
{
    const int row = blockIdx.x;
    __shared__ int   s_nbr[MAXNB];
    __shared__ float s_q[NHEADS][DHEAD];

    const int tid  = threadIdx.x;
    const int h    = tid >> 5;
    const int lane = tid & 31;
    const int m    = g_cnt[row];

    if (tid < MAXNB)
        s_nbr[tid] = (tid < m) ? g_nbr[row * MAXNB + tid] : 0;

    const float2 q2 = *(const float2*)&g_Q[row * DMODEL + h * DHEAD + lane * 2];
    ((float2*)s_q[h])[lane] = q2;
    __syncthreads();

    float score = __int_as_float(0xff800000);
    if (lane < m) {
        const float4* kp = (const float4*)&g_K[s_nbr[lane] * DMODEL + h * DHEAD];
        const float4* qp = (const float4*)&s_q[h][0];
        float acc = 0.f;
        #pragma unroll
        for (int c = 0; c < DHEAD / 4; ++c) {
            const float4 kv = kp[c];
            const float4 qv = qp[c];
            acc += kv.x * qv.x + kv.y * qv.y + kv.z * qv.z + kv.w * qv.w;
        }
        score = acc * 0.125f;
    }

    float mx = score;
    #pragma unroll
    for (int off = 16; off; off >>= 1)
        mx = fmaxf(mx, __shfl_xor_sync(0xffffffffu, mx, off));
    float p = __expf(score - mx);
    float sm = p;
    #pragma unroll
    for (int off = 16; off; off >>= 1)
        sm += __shfl_xor_sync(0xffffffffu, sm, off);
    const float pn = p / sm;

    float ox = 0.f, oy = 0.f;
    #pragma unroll
    for (int j = 0; j < MAXNB; ++j) {
        const float pj = __shfl_sync(0xffffffffu, pn, j);
        if (j < m) {
            const float2 v2 =
                *(const float2*)&g_V[s_nbr[j] * DMODEL + h * DHEAD + lane * 2];
            ox += pj * v2.x;
            oy += pj * v2.y;
        }
    }
    float2 o2; o2.x = ox; o2.y = oy;
    *(float2*)&g_A[row * DMODEL + h * DHEAD + lane * 2] = o2;
}

// ---------------------------------------------------------------------------
// Launch
// ---------------------------------------------------------------------------
extern "C" void kernel_launch(void* const* d_in, const int* in_sizes, int n_in,
                              void* d_out, int out_size)
{
    (void)in_sizes; (void)n_in; (void)out_size;
    const float* x   = (const float*)d_in[0];
    const float* pos = (const float*)d_in[1];
    const float* Wq  = (const float*)d_in[2];
    const float* bq  = (const float*)d_in[3];
    const float* Wk  = (const float*)d_in[4];
    const float* bk  = (const float*)d_in[5];
    const float* Wv  = (const float*)d_in[6];
    const float* bv  = (const float*)d_in[7];
    const float* Wo  = (const float*)d_in[8];
    const float* bo  = (const float*)d_in[9];
    float* out = (float*)d_out;

    const int topk_smem = 3 * SEQ * 4 + 8 * CAP * 8;
    cudaFuncSetAttribute(topk_kernel,
                         cudaFuncAttributeMaxDynamicSharedMemorySize, topk_smem);

    topk_kernel<<<MROWS / 8, 256, topk_smem>>>(pos);
    transpose_split_kernel<<<dim3(16, 16, 4), dim3(32, 32)>>>(Wq, Wk, Wv, Wo);
    split_x_kernel<<<(MROWS * DMODEL / 4) / 256, 256>>>(x);
    gemm_qkv_kernel<<<dim3(DMODEL / 128, MROWS / 128, 3), 256>>>(bq, bk, bv);
    attn_kernel<<<MROWS, 256>>>();
    split_a_kernel<<<(MROWS * DMODEL / 4) / 256, 256>>>();
    gemm_out_kernel<<<dim3(DMODEL / 128, MROWS / 128, 1), 256>>>(bo, out);
}